// round 11
// baseline (speedup 1.0000x reference)
#include <cuda_runtime.h>
#include <cstdint>

// ---------------- problem-size constants ----------------
#define NMAX   100000
#define EMAX   1600000
#define HF     128
#define GMAX   64

// ---------------- static device scratch (ONLY touched inside kernels) -----
__device__ float g_bufA[(size_t)NMAX * HF];   // P1, then h2
__device__ float g_bufB[(size_t)NMAX * HF];   // h1
__device__ int   g_deg[NMAX];
__device__ int   g_rowoff[NMAX + 1];
__device__ int   g_cursor[NMAX];
__device__ int   g_csrc[EMAX];
__device__ int   g_part[512];
__device__ float g_gf[GMAX * HF];

// ---------------- packed f32x2 helpers -----------------
static __device__ __forceinline__ uint64_t pack2(float x, float y) {
    uint64_t r;
    asm("mov.b64 %0, {%1, %2};" : "=l"(r) : "f"(x), "f"(y));
    return r;
}
static __device__ __forceinline__ void unpack2(uint64_t v, float& x, float& y) {
    asm("mov.b64 {%0, %1}, %2;" : "=f"(x), "=f"(y) : "l"(v));
}
static __device__ __forceinline__ void fma2(uint64_t& d, uint64_t a, uint64_t b) {
    asm("fma.rn.f32x2 %0, %1, %2, %0;" : "+l"(d) : "l"(a), "l"(b));
}

// ---------------- CSR build (stream 2) ----------------
__global__ void k_zero(int n) {
    int i = blockIdx.x * blockDim.x + threadIdx.x;
    if (i < n) g_deg[i] = 0;
    if (i < GMAX * HF) g_gf[i] = 0.f;
}

__global__ void k_hist4(const int* __restrict__ dst, int E) {
    int i4 = (blockIdx.x * blockDim.x + threadIdx.x) * 4;
    if (i4 + 4 <= E) {
        int4 d = *(const int4*)&dst[i4];
        atomicAdd(&g_deg[d.x], 1);
        atomicAdd(&g_deg[d.y], 1);
        atomicAdd(&g_deg[d.z], 1);
        atomicAdd(&g_deg[d.w], 1);
    } else {
        for (int i = i4; i < E; i++) atomicAdd(&g_deg[dst[i]], 1);
    }
}

__global__ void k_scan1(int n) {
    __shared__ int s[256];
    int i = blockIdx.x * 256 + threadIdx.x;
    s[threadIdx.x] = (i < n) ? g_deg[i] : 0;
    __syncthreads();
    for (int off = 128; off > 0; off >>= 1) {
        if (threadIdx.x < off) s[threadIdx.x] += s[threadIdx.x + off];
        __syncthreads();
    }
    if (threadIdx.x == 0) g_part[blockIdx.x] = s[0];
}
__global__ void k_scan2(int nb, int n) {
    __shared__ int s[512];
    int t = threadIdx.x;
    int v = (t < nb) ? g_part[t] : 0;
    s[t] = v;
    __syncthreads();
    for (int off = 1; off < 512; off <<= 1) {
        int x = s[t];
        int y = (t >= off) ? s[t - off] : 0;
        __syncthreads();
        s[t] = x + y;
        __syncthreads();
    }
    if (t < nb) g_part[t] = s[t] - v;
    if (t == 511) g_rowoff[n] = s[511];
}
__global__ void k_scan3(int n) {
    __shared__ int s[256];
    int t = threadIdx.x;
    int i = blockIdx.x * 256 + t;
    int v = (i < n) ? g_deg[i] : 0;
    s[t] = v;
    __syncthreads();
    for (int off = 1; off < 256; off <<= 1) {
        int x = s[t];
        int y = (t >= off) ? s[t - off] : 0;
        __syncthreads();
        s[t] = x + y;
        __syncthreads();
    }
    if (i < n) {
        int o = g_part[blockIdx.x] + s[t] - v;
        g_rowoff[i] = o;
        g_cursor[i] = o;
    }
}

__global__ void k_bucket4(const int* __restrict__ src, const int* __restrict__ dst, int E) {
    int i4 = (blockIdx.x * blockDim.x + threadIdx.x) * 4;
    if (i4 + 4 <= E) {
        int4 d = *(const int4*)&dst[i4];
        int4 sv = *(const int4*)&src[i4];
        int p0 = atomicAdd(&g_cursor[d.x], 1);
        int p1 = atomicAdd(&g_cursor[d.y], 1);
        int p2 = atomicAdd(&g_cursor[d.z], 1);
        int p3 = atomicAdd(&g_cursor[d.w], 1);
        g_csrc[p0] = sv.x;
        g_csrc[p1] = sv.y;
        g_csrc[p2] = sv.z;
        g_csrc[p3] = sv.w;
    } else {
        for (int i = i4; i < E; i++) {
            int p = atomicAdd(&g_cursor[dst[i]], 1);
            g_csrc[p] = src[i];
        }
    }
}

// ---------------- GEMM1: g_bufA = feat @ W1 (no epilogue) -----------------
#define AS_STRIDE 36
__global__ void __launch_bounds__(256) k_gemm(const float* __restrict__ A,
                                              const float* __restrict__ W, int M) {
    __shared__ float As[128 * AS_STRIDE];
    __shared__ float Ws[32 * 128];

    int tid = threadIdx.x;
    int tx = tid & 15;
    int ty = tid >> 4;
    int row0 = blockIdx.x * 128;
    float* __restrict__ out = g_bufA;

    uint64_t acc[8][4];
#pragma unroll
    for (int i = 0; i < 8; i++)
#pragma unroll
        for (int j = 0; j < 4; j++) acc[i][j] = 0ull;

    for (int kt = 0; kt < 4; kt++) {
        int k0 = kt * 32;
#pragma unroll
        for (int j = 0; j < 4; j++) {
            int lin = (j * 256 + tid) * 4;
            int r = lin >> 5;
            int c = lin & 31;
            float4 v = make_float4(0.f, 0.f, 0.f, 0.f);
            if (row0 + r < M)
                v = *(const float4*)&A[(size_t)(row0 + r) * 128 + k0 + c];
            *(float4*)&As[r * AS_STRIDE + c] = v;
        }
#pragma unroll
        for (int j = 0; j < 4; j++) {
            int lin = (j * 256 + tid) * 4;
            int r = lin >> 7;
            int c = lin & 127;
            *(float4*)&Ws[r * 128 + c] = *(const float4*)&W[(size_t)(k0 + r) * 128 + c];
        }
        __syncthreads();

#pragma unroll 8
        for (int kk = 0; kk < 32; kk++) {
            const uint64_t* wrow = (const uint64_t*)&Ws[kk * 128 + tx * 8];
            uint64_t w0 = wrow[0];
            uint64_t w1 = wrow[1];
            uint64_t w2 = wrow[2];
            uint64_t w3 = wrow[3];
#pragma unroll
            for (int i = 0; i < 8; i++) {
                float a = As[(ty * 8 + i) * AS_STRIDE + kk];
                uint64_t ad = pack2(a, a);
                fma2(acc[i][0], ad, w0);
                fma2(acc[i][1], ad, w1);
                fma2(acc[i][2], ad, w2);
                fma2(acc[i][3], ad, w3);
            }
        }
        __syncthreads();
    }

#pragma unroll
    for (int i = 0; i < 8; i++) {
        int r = row0 + ty * 8 + i;
        if (r < M) {
            float v[8];
#pragma unroll
            for (int j = 0; j < 4; j++)
                unpack2(acc[i][j], v[2 * j], v[2 * j + 1]);
            float4* orow = (float4*)&out[(size_t)r * 128 + tx * 8];
            orow[0] = make_float4(v[0], v[1], v[2], v[3]);
            orow[1] = make_float4(v[4], v[5], v[6], v[7]);
        }
    }
}

// ------- agg1: g_bufB = relu(agg(g_bufA) + b1), one warp per node ---------
// Software-pipelined: batch i's row loads in flight while batch i+1's
// indices are fetched (breaks the idx->row serial latency chain).
__global__ void k_agg(const float* __restrict__ bias, int n) {
    int gt = blockIdx.x * blockDim.x + threadIdx.x;
    int node = gt >> 5;
    if (node >= n) return;
    int lane = threadIdx.x & 31;
    const float4* __restrict__ in = (const float4*)g_bufA;

    int e   = g_rowoff[node];
    int end = g_rowoff[node + 1];
    float4 acc = make_float4(0.f, 0.f, 0.f, 0.f);

    int nb = (end - e) >> 3;   // full 8-edge batches
    int si[8];
    if (nb > 0) {
#pragma unroll
        for (int q = 0; q < 8; q++) si[q] = g_csrc[e + q];
    }
    for (int b = 0; b < nb; b++) {
        float4 v[8];
#pragma unroll
        for (int q = 0; q < 8; q++)
            v[q] = __ldg(&in[(size_t)si[q] * 32 + lane]);
        if (b + 1 < nb) {
#pragma unroll
            for (int q = 0; q < 8; q++) si[q] = g_csrc[e + 8 + q];
        }
        e += 8;
        acc.x += ((v[0].x + v[1].x) + (v[2].x + v[3].x)) + ((v[4].x + v[5].x) + (v[6].x + v[7].x));
        acc.y += ((v[0].y + v[1].y) + (v[2].y + v[3].y)) + ((v[4].y + v[5].y) + (v[6].y + v[7].y));
        acc.z += ((v[0].z + v[1].z) + (v[2].z + v[3].z)) + ((v[4].z + v[5].z) + (v[6].z + v[7].z));
        acc.w += ((v[0].w + v[1].w) + (v[2].w + v[3].w)) + ((v[4].w + v[5].w) + (v[6].w + v[7].w));
    }
    for (; e + 2 <= end; e += 2) {
        int s0 = g_csrc[e];
        int s1 = g_csrc[e + 1];
        float4 v0 = __ldg(&in[(size_t)s0 * 32 + lane]);
        float4 v1 = __ldg(&in[(size_t)s1 * 32 + lane]);
        acc.x += v0.x + v1.x;
        acc.y += v0.y + v1.y;
        acc.z += v0.z + v1.z;
        acc.w += v0.w + v1.w;
    }
    if (e < end) {
        int s0 = g_csrc[e];
        float4 v0 = __ldg(&in[(size_t)s0 * 32 + lane]);
        acc.x += v0.x; acc.y += v0.y; acc.z += v0.z; acc.w += v0.w;
    }
    float4 bb = __ldg(&((const float4*)bias)[lane]);
    acc.x = fmaxf(acc.x + bb.x, 0.f);
    acc.y = fmaxf(acc.y + bb.y, 0.f);
    acc.z = fmaxf(acc.z + bb.z, 0.f);
    acc.w = fmaxf(acc.w + bb.w, 0.f);
    ((float4*)g_bufB)[(size_t)node * 32 + lane] = acc;
}

// ------- fused layer 2: g_bufA = relu(agg(g_bufB) @ W2 + b2) --------------
// Phase A: MLP-16 gather with index prefetch pipeline. Phase B: f32x2 GEMM.
#define FA_STRIDE 132
#define SM_FUSED  (128 * FA_STRIDE * 4 + 32 * 128 * 4)   // 83968 bytes
__global__ void __launch_bounds__(256) k_fused(const float* __restrict__ W,
                                               const float* __restrict__ bias, int N) {
    extern __shared__ float smem[];
    float* As = smem;                      // [128][FA_STRIDE]
    float* Ws = smem + 128 * FA_STRIDE;    // [32][128]

    int tid = threadIdx.x;
    int wid = tid >> 5;
    int lane = tid & 31;
    int row0 = blockIdx.x * 128;
    const float4* __restrict__ in = (const float4*)g_bufB;
    float* __restrict__ out = g_bufA;

    // ---- Phase A: gather 16 nodes per warp into smem ----
    for (int j = 0; j < 16; j++) {
        int lr = wid * 16 + j;
        int node = row0 + lr;
        float4 acc = make_float4(0.f, 0.f, 0.f, 0.f);
        if (node < N) {
            int e   = g_rowoff[node];
            int end = g_rowoff[node + 1];
            int nb = (end - e) >> 4;   // full 16-edge batches
            int si[16];
            if (nb > 0) {
#pragma unroll
                for (int q = 0; q < 16; q++) si[q] = g_csrc[e + q];
            }
            for (int b = 0; b < nb; b++) {
                float4 v[16];
#pragma unroll
                for (int q = 0; q < 16; q++)
                    v[q] = __ldg(&in[(size_t)si[q] * 32 + lane]);
                if (b + 1 < nb) {
#pragma unroll
                    for (int q = 0; q < 16; q++) si[q] = g_csrc[e + 16 + q];
                }
                e += 16;
                float4 p0, p1;
                p0.x = ((v[0].x + v[1].x) + (v[2].x + v[3].x)) + ((v[4].x + v[5].x) + (v[6].x + v[7].x));
                p0.y = ((v[0].y + v[1].y) + (v[2].y + v[3].y)) + ((v[4].y + v[5].y) + (v[6].y + v[7].y));
                p0.z = ((v[0].z + v[1].z) + (v[2].z + v[3].z)) + ((v[4].z + v[5].z) + (v[6].z + v[7].z));
                p0.w = ((v[0].w + v[1].w) + (v[2].w + v[3].w)) + ((v[4].w + v[5].w) + (v[6].w + v[7].w));
                p1.x = ((v[8].x + v[9].x) + (v[10].x + v[11].x)) + ((v[12].x + v[13].x) + (v[14].x + v[15].x));
                p1.y = ((v[8].y + v[9].y) + (v[10].y + v[11].y)) + ((v[12].y + v[13].y) + (v[14].y + v[15].y));
                p1.z = ((v[8].z + v[9].z) + (v[10].z + v[11].z)) + ((v[12].z + v[13].z) + (v[14].z + v[15].z));
                p1.w = ((v[8].w + v[9].w) + (v[10].w + v[11].w)) + ((v[12].w + v[13].w) + (v[14].w + v[15].w));
                acc.x += p0.x + p1.x;
                acc.y += p0.y + p1.y;
                acc.z += p0.z + p1.z;
                acc.w += p0.w + p1.w;
            }
            for (; e + 2 <= end; e += 2) {
                int s0 = g_csrc[e];
                int s1 = g_csrc[e + 1];
                float4 v0 = __ldg(&in[(size_t)s0 * 32 + lane]);
                float4 v1 = __ldg(&in[(size_t)s1 * 32 + lane]);
                acc.x += v0.x + v1.x;
                acc.y += v0.y + v1.y;
                acc.z += v0.z + v1.z;
                acc.w += v0.w + v1.w;
            }
            if (e < end) {
                int s0 = g_csrc[e];
                float4 v0 = __ldg(&in[(size_t)s0 * 32 + lane]);
                acc.x += v0.x; acc.y += v0.y; acc.z += v0.z; acc.w += v0.w;
            }
        }
        *(float4*)&As[lr * FA_STRIDE + lane * 4] = acc;
    }
    __syncthreads();

    // ---- Phase B: GEMM from smem As, W tiles ----
    int tx = tid & 15;
    int ty = tid >> 4;

    uint64_t acc[8][4];
#pragma unroll
    for (int i = 0; i < 8; i++)
#pragma unroll
        for (int j = 0; j < 4; j++) acc[i][j] = 0ull;

    for (int kt = 0; kt < 4; kt++) {
        int k0 = kt * 32;
#pragma unroll
        for (int j = 0; j < 4; j++) {
            int lin = (j * 256 + tid) * 4;
            int r = lin >> 7;
            int c = lin & 127;
            *(float4*)&Ws[r * 128 + c] = *(const float4*)&W[(size_t)(k0 + r) * 128 + c];
        }
        __syncthreads();

#pragma unroll 8
        for (int kk = 0; kk < 32; kk++) {
            const uint64_t* wrow = (const uint64_t*)&Ws[kk * 128 + tx * 8];
            uint64_t w0 = wrow[0];
            uint64_t w1 = wrow[1];
            uint64_t w2 = wrow[2];
            uint64_t w3 = wrow[3];
#pragma unroll
            for (int i = 0; i < 8; i++) {
                float a = As[(ty * 8 + i) * FA_STRIDE + k0 + kk];
                uint64_t ad = pack2(a, a);
                fma2(acc[i][0], ad, w0);
                fma2(acc[i][1], ad, w1);
                fma2(acc[i][2], ad, w2);
                fma2(acc[i][3], ad, w3);
            }
        }
        __syncthreads();
    }

    float bb[8];
#pragma unroll
    for (int j = 0; j < 8; j++) bb[j] = __ldg(&bias[tx * 8 + j]);

#pragma unroll
    for (int i = 0; i < 8; i++) {
        int r = row0 + ty * 8 + i;
        if (r < N) {
            float v[8];
#pragma unroll
            for (int j = 0; j < 4; j++)
                unpack2(acc[i][j], v[2 * j], v[2 * j + 1]);
            float4 o0, o1;
            o0.x = fmaxf(v[0] + bb[0], 0.f);
            o0.y = fmaxf(v[1] + bb[1], 0.f);
            o0.z = fmaxf(v[2] + bb[2], 0.f);
            o0.w = fmaxf(v[3] + bb[3], 0.f);
            o1.x = fmaxf(v[4] + bb[4], 0.f);
            o1.y = fmaxf(v[5] + bb[5], 0.f);
            o1.z = fmaxf(v[6] + bb[6], 0.f);
            o1.w = fmaxf(v[7] + bb[7], 0.f);
            float4* orow = (float4*)&out[(size_t)r * 128 + tx * 8];
            orow[0] = o0;
            orow[1] = o1;
        }
    }
}

// ------- pooling: 8 CTAs per graph, atomic accumulate (reads h2 = g_bufA) -
__global__ void k_pool8(const int* __restrict__ gid, int n) {
    __shared__ int s_beg, s_end;
    int g = blockIdx.x >> 3;
    int slice = blockIdx.x & 7;
    if (threadIdx.x == 0) {
        int lo = 0, hi = n;
        while (lo < hi) { int mid = (lo + hi) >> 1; if (gid[mid] < g) lo = mid + 1; else hi = mid; }
        s_beg = lo;
        lo = 0; hi = n;
        while (lo < hi) { int mid = (lo + hi) >> 1; if (gid[mid] < g + 1) lo = mid + 1; else hi = mid; }
        s_end = lo;
    }
    __syncthreads();
    int beg = s_beg, end = s_end;
    int len = end - beg;
    int chunk = (len + 7) >> 3;
    int s = beg + slice * chunk;
    int e = s + chunk; if (e > end) e = end;
    if (s >= e) return;
    int f = threadIdx.x;
    const float* __restrict__ h = g_bufA;
    float acc = 0.f;
    int i = s;
    for (; i + 4 <= e; i += 4) {
        float a0 = h[(size_t)(i)     * 128 + f];
        float a1 = h[(size_t)(i + 1) * 128 + f];
        float a2 = h[(size_t)(i + 2) * 128 + f];
        float a3 = h[(size_t)(i + 3) * 128 + f];
        acc += (a0 + a1) + (a2 + a3);
    }
    for (; i < e; i++) acc += h[(size_t)i * 128 + f];
    atomicAdd(&g_gf[g * 128 + f], acc);
}

// ------- final projection ------------------
__global__ void k_final(const float* __restrict__ Wp, const float* __restrict__ bp,
                        float* __restrict__ out, const int* __restrict__ gid,
                        int n, int G, int C) {
    int tid = blockIdx.x * blockDim.x + threadIdx.x;
    if (tid >= G * C) return;
    int g = tid / C;
    int c = tid % C;
    int lo = 0, hi = n;
    while (lo < hi) { int mid = (lo + hi) >> 1; if (gid[mid] < g) lo = mid + 1; else hi = mid; }
    int beg = lo;
    lo = 0; hi = n;
    while (lo < hi) { int mid = (lo + hi) >> 1; if (gid[mid] < g + 1) lo = mid + 1; else hi = mid; }
    int cnt = lo - beg;
    float inv = 1.f / ((cnt > 0) ? (float)cnt : 1.f);
    float acc = 0.f;
#pragma unroll 8
    for (int k = 0; k < 128; k++)
        acc += (g_gf[g * 128 + k] * inv) * Wp[k * C + c];
    out[tid] = acc + bp[c];
}

// ---------------- launch --------------------------------------------------
extern "C" void kernel_launch(void* const* d_in, const int* in_sizes, int n_in,
                              void* d_out, int out_size) {
    const float* feat = (const float*)d_in[0];
    const float* W1   = (const float*)d_in[1];
    const float* b1   = (const float*)d_in[2];
    const float* W2   = (const float*)d_in[3];
    const float* b2   = (const float*)d_in[4];
    const float* Wp   = (const float*)d_in[5];
    const float* bp   = (const float*)d_in[6];
    const int*   src  = (const int*)d_in[7];
    const int*   dst  = (const int*)d_in[8];
    const int*   gid  = (const int*)d_in[9];

    int N = in_sizes[0] / HF;
    int E = in_sizes[7];
    int C = in_sizes[6];
    int G = out_size / C;

    static cudaStream_t s2 = nullptr;
    static cudaEvent_t evFork = nullptr, evCsr = nullptr;
    if (!s2) {
        cudaStreamCreateWithFlags(&s2, cudaStreamNonBlocking);
        cudaEventCreateWithFlags(&evFork, cudaEventDisableTiming);
        cudaEventCreateWithFlags(&evCsr, cudaEventDisableTiming);
        cudaFuncSetAttribute(k_fused, cudaFuncAttributeMaxDynamicSharedMemorySize, SM_FUSED);
    }

    int scanBlocks = (N + 255) / 256;

    // ---- fork: CSR build on s2, GEMM1 on main (single fork/join, proven) ----
    cudaEventRecord(evFork, 0);
    cudaStreamWaitEvent(s2, evFork, 0);

    k_zero   <<<(N + 255) / 256, 256, 0, s2>>>(N);
    k_hist4  <<<(E / 4 + 255) / 256, 256, 0, s2>>>(dst, E);
    k_scan1  <<<scanBlocks, 256, 0, s2>>>(N);
    k_scan2  <<<1, 512, 0, s2>>>(scanBlocks, N);
    k_scan3  <<<scanBlocks, 256, 0, s2>>>(N);
    k_bucket4<<<(E / 4 + 255) / 256, 256, 0, s2>>>(src, dst, E);
    cudaEventRecord(evCsr, s2);

    // GEMM1: P1 = feat @ W1 -> g_bufA (no CSR dependency)
    k_gemm<<<(N + 127) / 128, 256>>>(feat, W1, N);

    cudaStreamWaitEvent(0, evCsr, 0);

    // h1 = relu(agg(P1) + b1): g_bufA -> g_bufB
    k_agg<<<(N * 32 + 255) / 256, 256>>>(b1, N);

    // fused layer 2: h2 = relu(agg(h1) @ W2 + b2): g_bufB -> g_bufA
    k_fused<<<(N + 127) / 128, 256, SM_FUSED>>>(W2, b2, N);

    // readout (reads g_bufA = h2)
    k_pool8<<<G * 8, 128>>>(gid, N);
    k_final<<<(G * C + 255) / 256, 256>>>(Wp, bp, (float*)d_out, gid, N, G, C);
}

// round 12
// speedup vs baseline: 1.0024x; 1.0024x over previous
#include <cuda_runtime.h>
#include <cstdint>

// ---------------- problem-size constants ----------------
#define NMAX   100000
#define EMAX   1600000
#define HF     128
#define GMAX   64

// ---------------- static device scratch (ONLY touched inside kernels) -----
__device__ float g_bufA[(size_t)NMAX * HF];   // P1, then h2
__device__ float g_bufB[(size_t)NMAX * HF];   // h1
__device__ int   g_deg[NMAX];
__device__ int   g_rowoff[NMAX + 1];
__device__ int   g_cursor[NMAX];
__device__ int   g_csrc[EMAX];
__device__ int   g_part[512];
__device__ float g_gf[GMAX * HF];

// ---------------- packed f32x2 helpers -----------------
static __device__ __forceinline__ uint64_t pack2(float x, float y) {
    uint64_t r;
    asm("mov.b64 %0, {%1, %2};" : "=l"(r) : "f"(x), "f"(y));
    return r;
}
static __device__ __forceinline__ void unpack2(uint64_t v, float& x, float& y) {
    asm("mov.b64 {%0, %1}, %2;" : "=f"(x), "=f"(y) : "l"(v));
}
static __device__ __forceinline__ void fma2(uint64_t& d, uint64_t a, uint64_t b) {
    asm("fma.rn.f32x2 %0, %1, %2, %0;" : "+l"(d) : "l"(a), "l"(b));
}

// ---------------- CSR build (stream 2) ----------------
__global__ void k_zero(int n) {
    int i = blockIdx.x * blockDim.x + threadIdx.x;
    if (i < n) g_deg[i] = 0;
    if (i < GMAX * HF) g_gf[i] = 0.f;
}

__global__ void k_hist4(const int* __restrict__ dst, int E) {
    int i4 = (blockIdx.x * blockDim.x + threadIdx.x) * 4;
    if (i4 + 4 <= E) {
        int4 d = *(const int4*)&dst[i4];
        atomicAdd(&g_deg[d.x], 1);
        atomicAdd(&g_deg[d.y], 1);
        atomicAdd(&g_deg[d.z], 1);
        atomicAdd(&g_deg[d.w], 1);
    } else {
        for (int i = i4; i < E; i++) atomicAdd(&g_deg[dst[i]], 1);
    }
}

__global__ void k_scan1(int n) {
    __shared__ int s[256];
    int i = blockIdx.x * 256 + threadIdx.x;
    s[threadIdx.x] = (i < n) ? g_deg[i] : 0;
    __syncthreads();
    for (int off = 128; off > 0; off >>= 1) {
        if (threadIdx.x < off) s[threadIdx.x] += s[threadIdx.x + off];
        __syncthreads();
    }
    if (threadIdx.x == 0) g_part[blockIdx.x] = s[0];
}
__global__ void k_scan2(int nb, int n) {
    __shared__ int s[512];
    int t = threadIdx.x;
    int v = (t < nb) ? g_part[t] : 0;
    s[t] = v;
    __syncthreads();
    for (int off = 1; off < 512; off <<= 1) {
        int x = s[t];
        int y = (t >= off) ? s[t - off] : 0;
        __syncthreads();
        s[t] = x + y;
        __syncthreads();
    }
    if (t < nb) g_part[t] = s[t] - v;
    if (t == 511) g_rowoff[n] = s[511];
}
__global__ void k_scan3(int n) {
    __shared__ int s[256];
    int t = threadIdx.x;
    int i = blockIdx.x * 256 + t;
    int v = (i < n) ? g_deg[i] : 0;
    s[t] = v;
    __syncthreads();
    for (int off = 1; off < 256; off <<= 1) {
        int x = s[t];
        int y = (t >= off) ? s[t - off] : 0;
        __syncthreads();
        s[t] = x + y;
        __syncthreads();
    }
    if (i < n) {
        int o = g_part[blockIdx.x] + s[t] - v;
        g_rowoff[i] = o;
        g_cursor[i] = o;
    }
}

__global__ void k_bucket4(const int* __restrict__ src, const int* __restrict__ dst, int E) {
    int i4 = (blockIdx.x * blockDim.x + threadIdx.x) * 4;
    if (i4 + 4 <= E) {
        int4 d = *(const int4*)&dst[i4];
        int4 sv = *(const int4*)&src[i4];
        int p0 = atomicAdd(&g_cursor[d.x], 1);
        int p1 = atomicAdd(&g_cursor[d.y], 1);
        int p2 = atomicAdd(&g_cursor[d.z], 1);
        int p3 = atomicAdd(&g_cursor[d.w], 1);
        g_csrc[p0] = sv.x;
        g_csrc[p1] = sv.y;
        g_csrc[p2] = sv.z;
        g_csrc[p3] = sv.w;
    } else {
        for (int i = i4; i < E; i++) {
            int p = atomicAdd(&g_cursor[dst[i]], 1);
            g_csrc[p] = src[i];
        }
    }
}

// ---------------- GEMM1: g_bufA = feat @ W1 (no epilogue) -----------------
#define AS_STRIDE 36
__global__ void __launch_bounds__(256) k_gemm(const float* __restrict__ A,
                                              const float* __restrict__ W, int M) {
    __shared__ float As[128 * AS_STRIDE];
    __shared__ float Ws[32 * 128];

    int tid = threadIdx.x;
    int tx = tid & 15;
    int ty = tid >> 4;
    int row0 = blockIdx.x * 128;
    float* __restrict__ out = g_bufA;

    uint64_t acc[8][4];
#pragma unroll
    for (int i = 0; i < 8; i++)
#pragma unroll
        for (int j = 0; j < 4; j++) acc[i][j] = 0ull;

    for (int kt = 0; kt < 4; kt++) {
        int k0 = kt * 32;
#pragma unroll
        for (int j = 0; j < 4; j++) {
            int lin = (j * 256 + tid) * 4;
            int r = lin >> 5;
            int c = lin & 31;
            float4 v = make_float4(0.f, 0.f, 0.f, 0.f);
            if (row0 + r < M)
                v = *(const float4*)&A[(size_t)(row0 + r) * 128 + k0 + c];
            *(float4*)&As[r * AS_STRIDE + c] = v;
        }
#pragma unroll
        for (int j = 0; j < 4; j++) {
            int lin = (j * 256 + tid) * 4;
            int r = lin >> 7;
            int c = lin & 127;
            *(float4*)&Ws[r * 128 + c] = *(const float4*)&W[(size_t)(k0 + r) * 128 + c];
        }
        __syncthreads();

#pragma unroll 8
        for (int kk = 0; kk < 32; kk++) {
            const uint64_t* wrow = (const uint64_t*)&Ws[kk * 128 + tx * 8];
            uint64_t w0 = wrow[0];
            uint64_t w1 = wrow[1];
            uint64_t w2 = wrow[2];
            uint64_t w3 = wrow[3];
#pragma unroll
            for (int i = 0; i < 8; i++) {
                float a = As[(ty * 8 + i) * AS_STRIDE + kk];
                uint64_t ad = pack2(a, a);
                fma2(acc[i][0], ad, w0);
                fma2(acc[i][1], ad, w1);
                fma2(acc[i][2], ad, w2);
                fma2(acc[i][3], ad, w3);
            }
        }
        __syncthreads();
    }

#pragma unroll
    for (int i = 0; i < 8; i++) {
        int r = row0 + ty * 8 + i;
        if (r < M) {
            float v[8];
#pragma unroll
            for (int j = 0; j < 4; j++)
                unpack2(acc[i][j], v[2 * j], v[2 * j + 1]);
            float4* orow = (float4*)&out[(size_t)r * 128 + tx * 8];
            orow[0] = make_float4(v[0], v[1], v[2], v[3]);
            orow[1] = make_float4(v[4], v[5], v[6], v[7]);
        }
    }
}

// ------- agg1: g_bufB = relu(agg(g_bufA) + b1), one warp per node ---------
// (R10 form: straight MLP-8 batches, no index prefetch — prefetch regressed)
__global__ void k_agg(const float* __restrict__ bias, int n) {
    int gt = blockIdx.x * blockDim.x + threadIdx.x;
    int node = gt >> 5;
    if (node >= n) return;
    int lane = threadIdx.x & 31;
    const float4* __restrict__ in = (const float4*)g_bufA;

    int e   = g_rowoff[node];
    int end = g_rowoff[node + 1];
    float4 acc = make_float4(0.f, 0.f, 0.f, 0.f);

    for (; e + 8 <= end; e += 8) {
        int s0 = g_csrc[e];
        int s1 = g_csrc[e + 1];
        int s2 = g_csrc[e + 2];
        int s3 = g_csrc[e + 3];
        int s4 = g_csrc[e + 4];
        int s5 = g_csrc[e + 5];
        int s6 = g_csrc[e + 6];
        int s7 = g_csrc[e + 7];
        float4 v0 = __ldg(&in[(size_t)s0 * 32 + lane]);
        float4 v1 = __ldg(&in[(size_t)s1 * 32 + lane]);
        float4 v2 = __ldg(&in[(size_t)s2 * 32 + lane]);
        float4 v3 = __ldg(&in[(size_t)s3 * 32 + lane]);
        float4 v4 = __ldg(&in[(size_t)s4 * 32 + lane]);
        float4 v5 = __ldg(&in[(size_t)s5 * 32 + lane]);
        float4 v6 = __ldg(&in[(size_t)s6 * 32 + lane]);
        float4 v7 = __ldg(&in[(size_t)s7 * 32 + lane]);
        acc.x += ((v0.x + v1.x) + (v2.x + v3.x)) + ((v4.x + v5.x) + (v6.x + v7.x));
        acc.y += ((v0.y + v1.y) + (v2.y + v3.y)) + ((v4.y + v5.y) + (v6.y + v7.y));
        acc.z += ((v0.z + v1.z) + (v2.z + v3.z)) + ((v4.z + v5.z) + (v6.z + v7.z));
        acc.w += ((v0.w + v1.w) + (v2.w + v3.w)) + ((v4.w + v5.w) + (v6.w + v7.w));
    }
    for (; e + 2 <= end; e += 2) {
        int s0 = g_csrc[e];
        int s1 = g_csrc[e + 1];
        float4 v0 = __ldg(&in[(size_t)s0 * 32 + lane]);
        float4 v1 = __ldg(&in[(size_t)s1 * 32 + lane]);
        acc.x += v0.x + v1.x;
        acc.y += v0.y + v1.y;
        acc.z += v0.z + v1.z;
        acc.w += v0.w + v1.w;
    }
    if (e < end) {
        int s0 = g_csrc[e];
        float4 v0 = __ldg(&in[(size_t)s0 * 32 + lane]);
        acc.x += v0.x; acc.y += v0.y; acc.z += v0.z; acc.w += v0.w;
    }
    float4 bb = __ldg(&((const float4*)bias)[lane]);
    acc.x = fmaxf(acc.x + bb.x, 0.f);
    acc.y = fmaxf(acc.y + bb.y, 0.f);
    acc.z = fmaxf(acc.z + bb.z, 0.f);
    acc.w = fmaxf(acc.w + bb.w, 0.f);
    ((float4*)g_bufB)[(size_t)node * 32 + lane] = acc;
}

// ------- fused layer 2: g_bufA = relu(agg(g_bufB) @ W2 + b2) --------------
// 64-node tiles -> 49KB smem -> 4 CTAs/SM -> 32 gather warps/SM (2x R10).
// Phase A: each warp gathers 8 nodes (R10 MLP-16 loop, no prefetch).
// Phase B: 64x128 GEMM tile, 4 rows x 8 cols per thread.
#define FA_STRIDE 132
#define SM_FUSED  (64 * FA_STRIDE * 4 + 32 * 128 * 4)   // 33792 + 16384 = 50176
__global__ void __launch_bounds__(256) k_fused(const float* __restrict__ W,
                                               const float* __restrict__ bias, int N) {
    extern __shared__ float smem[];
    float* As = smem;                     // [64][FA_STRIDE]
    float* Ws = smem + 64 * FA_STRIDE;    // [32][128]

    int tid = threadIdx.x;
    int wid = tid >> 5;
    int lane = tid & 31;
    int row0 = blockIdx.x * 64;
    const float4* __restrict__ in = (const float4*)g_bufB;
    float* __restrict__ out = g_bufA;

    // ---- Phase A: gather 8 nodes per warp into smem, MLP-16 ----
    for (int j = 0; j < 8; j++) {
        int lr = wid * 8 + j;
        int node = row0 + lr;
        float4 acc = make_float4(0.f, 0.f, 0.f, 0.f);
        if (node < N) {
            int e   = g_rowoff[node];
            int end = g_rowoff[node + 1];
            for (; e + 16 <= end; e += 16) {
                int si[16];
#pragma unroll
                for (int q = 0; q < 16; q++) si[q] = g_csrc[e + q];
                float4 v[16];
#pragma unroll
                for (int q = 0; q < 16; q++)
                    v[q] = __ldg(&in[(size_t)si[q] * 32 + lane]);
                float4 p0, p1;
                p0.x = ((v[0].x + v[1].x) + (v[2].x + v[3].x)) + ((v[4].x + v[5].x) + (v[6].x + v[7].x));
                p0.y = ((v[0].y + v[1].y) + (v[2].y + v[3].y)) + ((v[4].y + v[5].y) + (v[6].y + v[7].y));
                p0.z = ((v[0].z + v[1].z) + (v[2].z + v[3].z)) + ((v[4].z + v[5].z) + (v[6].z + v[7].z));
                p0.w = ((v[0].w + v[1].w) + (v[2].w + v[3].w)) + ((v[4].w + v[5].w) + (v[6].w + v[7].w));
                p1.x = ((v[8].x + v[9].x) + (v[10].x + v[11].x)) + ((v[12].x + v[13].x) + (v[14].x + v[15].x));
                p1.y = ((v[8].y + v[9].y) + (v[10].y + v[11].y)) + ((v[12].y + v[13].y) + (v[14].y + v[15].y));
                p1.z = ((v[8].z + v[9].z) + (v[10].z + v[11].z)) + ((v[12].z + v[13].z) + (v[14].z + v[15].z));
                p1.w = ((v[8].w + v[9].w) + (v[10].w + v[11].w)) + ((v[12].w + v[13].w) + (v[14].w + v[15].w));
                acc.x += p0.x + p1.x;
                acc.y += p0.y + p1.y;
                acc.z += p0.z + p1.z;
                acc.w += p0.w + p1.w;
            }
            for (; e + 8 <= end; e += 8) {
                int s0 = g_csrc[e];
                int s1 = g_csrc[e + 1];
                int s2 = g_csrc[e + 2];
                int s3 = g_csrc[e + 3];
                int s4 = g_csrc[e + 4];
                int s5 = g_csrc[e + 5];
                int s6 = g_csrc[e + 6];
                int s7 = g_csrc[e + 7];
                float4 v0 = __ldg(&in[(size_t)s0 * 32 + lane]);
                float4 v1 = __ldg(&in[(size_t)s1 * 32 + lane]);
                float4 v2 = __ldg(&in[(size_t)s2 * 32 + lane]);
                float4 v3 = __ldg(&in[(size_t)s3 * 32 + lane]);
                float4 v4 = __ldg(&in[(size_t)s4 * 32 + lane]);
                float4 v5 = __ldg(&in[(size_t)s5 * 32 + lane]);
                float4 v6 = __ldg(&in[(size_t)s6 * 32 + lane]);
                float4 v7 = __ldg(&in[(size_t)s7 * 32 + lane]);
                acc.x += ((v0.x + v1.x) + (v2.x + v3.x)) + ((v4.x + v5.x) + (v6.x + v7.x));
                acc.y += ((v0.y + v1.y) + (v2.y + v3.y)) + ((v4.y + v5.y) + (v6.y + v7.y));
                acc.z += ((v0.z + v1.z) + (v2.z + v3.z)) + ((v4.z + v5.z) + (v6.z + v7.z));
                acc.w += ((v0.w + v1.w) + (v2.w + v3.w)) + ((v4.w + v5.w) + (v6.w + v7.w));
            }
            for (; e + 2 <= end; e += 2) {
                int s0 = g_csrc[e];
                int s1 = g_csrc[e + 1];
                float4 v0 = __ldg(&in[(size_t)s0 * 32 + lane]);
                float4 v1 = __ldg(&in[(size_t)s1 * 32 + lane]);
                acc.x += v0.x + v1.x;
                acc.y += v0.y + v1.y;
                acc.z += v0.z + v1.z;
                acc.w += v0.w + v1.w;
            }
            if (e < end) {
                int s0 = g_csrc[e];
                float4 v0 = __ldg(&in[(size_t)s0 * 32 + lane]);
                acc.x += v0.x; acc.y += v0.y; acc.z += v0.z; acc.w += v0.w;
            }
        }
        *(float4*)&As[lr * FA_STRIDE + lane * 4] = acc;
    }
    __syncthreads();

    // ---- Phase B: 64x128 GEMM from smem As, W tiles ----
    int tx = tid & 15;       // cols [tx*8, tx*8+8)
    int ty = tid >> 4;       // rows [ty*4, ty*4+4)

    uint64_t acc[4][4];
#pragma unroll
    for (int i = 0; i < 4; i++)
#pragma unroll
        for (int j = 0; j < 4; j++) acc[i][j] = 0ull;

    for (int kt = 0; kt < 4; kt++) {
        int k0 = kt * 32;
#pragma unroll
        for (int j = 0; j < 4; j++) {
            int lin = (j * 256 + tid) * 4;
            int r = lin >> 7;
            int c = lin & 127;
            *(float4*)&Ws[r * 128 + c] = *(const float4*)&W[(size_t)(k0 + r) * 128 + c];
        }
        __syncthreads();

#pragma unroll 8
        for (int kk = 0; kk < 32; kk++) {
            const uint64_t* wrow = (const uint64_t*)&Ws[kk * 128 + tx * 8];
            uint64_t w0 = wrow[0];
            uint64_t w1 = wrow[1];
            uint64_t w2 = wrow[2];
            uint64_t w3 = wrow[3];
#pragma unroll
            for (int i = 0; i < 4; i++) {
                float a = As[(ty * 4 + i) * FA_STRIDE + k0 + kk];
                uint64_t ad = pack2(a, a);
                fma2(acc[i][0], ad, w0);
                fma2(acc[i][1], ad, w1);
                fma2(acc[i][2], ad, w2);
                fma2(acc[i][3], ad, w3);
            }
        }
        __syncthreads();
    }

    float bb[8];
#pragma unroll
    for (int j = 0; j < 8; j++) bb[j] = __ldg(&bias[tx * 8 + j]);

#pragma unroll
    for (int i = 0; i < 4; i++) {
        int r = row0 + ty * 4 + i;
        if (r < N) {
            float v[8];
#pragma unroll
            for (int j = 0; j < 4; j++)
                unpack2(acc[i][j], v[2 * j], v[2 * j + 1]);
            float4 o0, o1;
            o0.x = fmaxf(v[0] + bb[0], 0.f);
            o0.y = fmaxf(v[1] + bb[1], 0.f);
            o0.z = fmaxf(v[2] + bb[2], 0.f);
            o0.w = fmaxf(v[3] + bb[3], 0.f);
            o1.x = fmaxf(v[4] + bb[4], 0.f);
            o1.y = fmaxf(v[5] + bb[5], 0.f);
            o1.z = fmaxf(v[6] + bb[6], 0.f);
            o1.w = fmaxf(v[7] + bb[7], 0.f);
            float4* orow = (float4*)&out[(size_t)r * 128 + tx * 8];
            orow[0] = o0;
            orow[1] = o1;
        }
    }
}

// ------- pooling: 8 CTAs per graph, atomic accumulate (reads h2 = g_bufA) -
__global__ void k_pool8(const int* __restrict__ gid, int n) {
    __shared__ int s_beg, s_end;
    int g = blockIdx.x >> 3;
    int slice = blockIdx.x & 7;
    if (threadIdx.x == 0) {
        int lo = 0, hi = n;
        while (lo < hi) { int mid = (lo + hi) >> 1; if (gid[mid] < g) lo = mid + 1; else hi = mid; }
        s_beg = lo;
        lo = 0; hi = n;
        while (lo < hi) { int mid = (lo + hi) >> 1; if (gid[mid] < g + 1) lo = mid + 1; else hi = mid; }
        s_end = lo;
    }
    __syncthreads();
    int beg = s_beg, end = s_end;
    int len = end - beg;
    int chunk = (len + 7) >> 3;
    int s = beg + slice * chunk;
    int e = s + chunk; if (e > end) e = end;
    if (s >= e) return;
    int f = threadIdx.x;
    const float* __restrict__ h = g_bufA;
    float acc = 0.f;
    int i = s;
    for (; i + 4 <= e; i += 4) {
        float a0 = h[(size_t)(i)     * 128 + f];
        float a1 = h[(size_t)(i + 1) * 128 + f];
        float a2 = h[(size_t)(i + 2) * 128 + f];
        float a3 = h[(size_t)(i + 3) * 128 + f];
        acc += (a0 + a1) + (a2 + a3);
    }
    for (; i < e; i++) acc += h[(size_t)i * 128 + f];
    atomicAdd(&g_gf[g * 128 + f], acc);
}

// ------- final projection ------------------
__global__ void k_final(const float* __restrict__ Wp, const float* __restrict__ bp,
                        float* __restrict__ out, const int* __restrict__ gid,
                        int n, int G, int C) {
    int tid = blockIdx.x * blockDim.x + threadIdx.x;
    if (tid >= G * C) return;
    int g = tid / C;
    int c = tid % C;
    int lo = 0, hi = n;
    while (lo < hi) { int mid = (lo + hi) >> 1; if (gid[mid] < g) lo = mid + 1; else hi = mid; }
    int beg = lo;
    lo = 0; hi = n;
    while (lo < hi) { int mid = (lo + hi) >> 1; if (gid[mid] < g + 1) lo = mid + 1; else hi = mid; }
    int cnt = lo - beg;
    float inv = 1.f / ((cnt > 0) ? (float)cnt : 1.f);
    float acc = 0.f;
#pragma unroll 8
    for (int k = 0; k < 128; k++)
        acc += (g_gf[g * 128 + k] * inv) * Wp[k * C + c];
    out[tid] = acc + bp[c];
}

// ---------------- launch --------------------------------------------------
extern "C" void kernel_launch(void* const* d_in, const int* in_sizes, int n_in,
                              void* d_out, int out_size) {
    const float* feat = (const float*)d_in[0];
    const float* W1   = (const float*)d_in[1];
    const float* b1   = (const float*)d_in[2];
    const float* W2   = (const float*)d_in[3];
    const float* b2   = (const float*)d_in[4];
    const float* Wp   = (const float*)d_in[5];
    const float* bp   = (const float*)d_in[6];
    const int*   src  = (const int*)d_in[7];
    const int*   dst  = (const int*)d_in[8];
    const int*   gid  = (const int*)d_in[9];

    int N = in_sizes[0] / HF;
    int E = in_sizes[7];
    int C = in_sizes[6];
    int G = out_size / C;

    static cudaStream_t s2 = nullptr;
    static cudaEvent_t evFork = nullptr, evCsr = nullptr;
    if (!s2) {
        cudaStreamCreateWithFlags(&s2, cudaStreamNonBlocking);
        cudaEventCreateWithFlags(&evFork, cudaEventDisableTiming);
        cudaEventCreateWithFlags(&evCsr, cudaEventDisableTiming);
        cudaFuncSetAttribute(k_fused, cudaFuncAttributeMaxDynamicSharedMemorySize, SM_FUSED);
    }

    int scanBlocks = (N + 255) / 256;

    // ---- fork: CSR build on s2, GEMM1 on main (single fork/join, proven) ----
    cudaEventRecord(evFork, 0);
    cudaStreamWaitEvent(s2, evFork, 0);

    k_zero   <<<(N + 255) / 256, 256, 0, s2>>>(N);
    k_hist4  <<<(E / 4 + 255) / 256, 256, 0, s2>>>(dst, E);
    k_scan1  <<<scanBlocks, 256, 0, s2>>>(N);
    k_scan2  <<<1, 512, 0, s2>>>(scanBlocks, N);
    k_scan3  <<<scanBlocks, 256, 0, s2>>>(N);
    k_bucket4<<<(E / 4 + 255) / 256, 256, 0, s2>>>(src, dst, E);
    cudaEventRecord(evCsr, s2);

    // GEMM1: P1 = feat @ W1 -> g_bufA (no CSR dependency)
    k_gemm<<<(N + 127) / 128, 256>>>(feat, W1, N);

    cudaStreamWaitEvent(0, evCsr, 0);

    // h1 = relu(agg(P1) + b1): g_bufA -> g_bufB
    k_agg<<<(N * 32 + 255) / 256, 256>>>(b1, N);

    // fused layer 2: h2 = relu(agg(h1) @ W2 + b2): g_bufB -> g_bufA
    k_fused<<<(N + 63) / 64, 256, SM_FUSED>>>(W2, b2, N);

    // readout (reads g_bufA = h2)
    k_pool8<<<G * 8, 128>>>(gid, N);
    k_final<<<(G * C + 255) / 256, 256>>>(Wp, bp, (float*)d_out, gid, N, G, C);
}

// round 13
// speedup vs baseline: 1.1296x; 1.1270x over previous
#include <cuda_runtime.h>
#include <cuda_bf16.h>
#include <cstdint>

// ---------------- problem-size constants ----------------
#define NMAX   100000
#define EMAX   1600000
#define HF     128
#define GMAX   64

// ---------------- static device scratch (ONLY touched inside kernels) -----
__device__ __nv_bfloat16 g_p16[(size_t)NMAX * HF];   // P1 in bf16 (gather source L1)
__device__ __nv_bfloat16 g_h16[(size_t)NMAX * HF];   // h1 in bf16 (gather source L2)
__device__ float g_bufA[(size_t)NMAX * HF];          // h2 (fp32, pooled)
__device__ int   g_deg[NMAX];
__device__ int   g_rowoff[NMAX + 1];
__device__ int   g_cursor[NMAX];
__device__ int   g_csrc[EMAX];
__device__ int   g_part[512];
__device__ float g_gf[GMAX * HF];

// ---------------- packed helpers -----------------
static __device__ __forceinline__ uint64_t pack2(float x, float y) {
    uint64_t r;
    asm("mov.b64 %0, {%1, %2};" : "=l"(r) : "f"(x), "f"(y));
    return r;
}
static __device__ __forceinline__ void unpack2(uint64_t v, float& x, float& y) {
    asm("mov.b64 {%0, %1}, %2;" : "=f"(x), "=f"(y) : "l"(v));
}
static __device__ __forceinline__ void fma2(uint64_t& d, uint64_t a, uint64_t b) {
    asm("fma.rn.f32x2 %0, %1, %2, %0;" : "+l"(d) : "l"(a), "l"(b));
}
static __device__ __forceinline__ float2 bf2f(uint32_t u) {
    __nv_bfloat162 b = *reinterpret_cast<__nv_bfloat162*>(&u);
    return __bfloat1622float2(b);
}
static __device__ __forceinline__ uint32_t f2bf(float x, float y) {
    __nv_bfloat162 b = __float22bfloat162_rn(make_float2(x, y));
    return *reinterpret_cast<uint32_t*>(&b);
}

// ---------------- CSR build (stream 2) ----------------
__global__ void k_zero(int n) {
    int i = blockIdx.x * blockDim.x + threadIdx.x;
    if (i < n) g_deg[i] = 0;
    if (i < GMAX * HF) g_gf[i] = 0.f;
}

__global__ void k_hist4(const int* __restrict__ dst, int E) {
    int i4 = (blockIdx.x * blockDim.x + threadIdx.x) * 4;
    if (i4 + 4 <= E) {
        int4 d = *(const int4*)&dst[i4];
        atomicAdd(&g_deg[d.x], 1);
        atomicAdd(&g_deg[d.y], 1);
        atomicAdd(&g_deg[d.z], 1);
        atomicAdd(&g_deg[d.w], 1);
    } else {
        for (int i = i4; i < E; i++) atomicAdd(&g_deg[dst[i]], 1);
    }
}

__global__ void k_scan1(int n) {
    __shared__ int s[256];
    int i = blockIdx.x * 256 + threadIdx.x;
    s[threadIdx.x] = (i < n) ? g_deg[i] : 0;
    __syncthreads();
    for (int off = 128; off > 0; off >>= 1) {
        if (threadIdx.x < off) s[threadIdx.x] += s[threadIdx.x + off];
        __syncthreads();
    }
    if (threadIdx.x == 0) g_part[blockIdx.x] = s[0];
}
__global__ void k_scan2(int nb, int n) {
    __shared__ int s[512];
    int t = threadIdx.x;
    int v = (t < nb) ? g_part[t] : 0;
    s[t] = v;
    __syncthreads();
    for (int off = 1; off < 512; off <<= 1) {
        int x = s[t];
        int y = (t >= off) ? s[t - off] : 0;
        __syncthreads();
        s[t] = x + y;
        __syncthreads();
    }
    if (t < nb) g_part[t] = s[t] - v;
    if (t == 511) g_rowoff[n] = s[511];
}
__global__ void k_scan3(int n) {
    __shared__ int s[256];
    int t = threadIdx.x;
    int i = blockIdx.x * 256 + t;
    int v = (i < n) ? g_deg[i] : 0;
    s[t] = v;
    __syncthreads();
    for (int off = 1; off < 256; off <<= 1) {
        int x = s[t];
        int y = (t >= off) ? s[t - off] : 0;
        __syncthreads();
        s[t] = x + y;
        __syncthreads();
    }
    if (i < n) {
        int o = g_part[blockIdx.x] + s[t] - v;
        g_rowoff[i] = o;
        g_cursor[i] = o;
    }
}

__global__ void k_bucket4(const int* __restrict__ src, const int* __restrict__ dst, int E) {
    int i4 = (blockIdx.x * blockDim.x + threadIdx.x) * 4;
    if (i4 + 4 <= E) {
        int4 d = *(const int4*)&dst[i4];
        int4 sv = *(const int4*)&src[i4];
        int p0 = atomicAdd(&g_cursor[d.x], 1);
        int p1 = atomicAdd(&g_cursor[d.y], 1);
        int p2 = atomicAdd(&g_cursor[d.z], 1);
        int p3 = atomicAdd(&g_cursor[d.w], 1);
        g_csrc[p0] = sv.x;
        g_csrc[p1] = sv.y;
        g_csrc[p2] = sv.z;
        g_csrc[p3] = sv.w;
    } else {
        for (int i = i4; i < E; i++) {
            int p = atomicAdd(&g_cursor[dst[i]], 1);
            g_csrc[p] = src[i];
        }
    }
}

// ---------------- GEMM1: g_p16 = bf16(feat @ W1) --------------------------
#define AS_STRIDE 36
__global__ void __launch_bounds__(256) k_gemm(const float* __restrict__ A,
                                              const float* __restrict__ W, int M) {
    __shared__ float As[128 * AS_STRIDE];
    __shared__ float Ws[32 * 128];

    int tid = threadIdx.x;
    int tx = tid & 15;
    int ty = tid >> 4;
    int row0 = blockIdx.x * 128;

    uint64_t acc[8][4];
#pragma unroll
    for (int i = 0; i < 8; i++)
#pragma unroll
        for (int j = 0; j < 4; j++) acc[i][j] = 0ull;

    for (int kt = 0; kt < 4; kt++) {
        int k0 = kt * 32;
#pragma unroll
        for (int j = 0; j < 4; j++) {
            int lin = (j * 256 + tid) * 4;
            int r = lin >> 5;
            int c = lin & 31;
            float4 v = make_float4(0.f, 0.f, 0.f, 0.f);
            if (row0 + r < M)
                v = *(const float4*)&A[(size_t)(row0 + r) * 128 + k0 + c];
            *(float4*)&As[r * AS_STRIDE + c] = v;
        }
#pragma unroll
        for (int j = 0; j < 4; j++) {
            int lin = (j * 256 + tid) * 4;
            int r = lin >> 7;
            int c = lin & 127;
            *(float4*)&Ws[r * 128 + c] = *(const float4*)&W[(size_t)(k0 + r) * 128 + c];
        }
        __syncthreads();

#pragma unroll 8
        for (int kk = 0; kk < 32; kk++) {
            const uint64_t* wrow = (const uint64_t*)&Ws[kk * 128 + tx * 8];
            uint64_t w0 = wrow[0];
            uint64_t w1 = wrow[1];
            uint64_t w2 = wrow[2];
            uint64_t w3 = wrow[3];
#pragma unroll
            for (int i = 0; i < 8; i++) {
                float a = As[(ty * 8 + i) * AS_STRIDE + kk];
                uint64_t ad = pack2(a, a);
                fma2(acc[i][0], ad, w0);
                fma2(acc[i][1], ad, w1);
                fma2(acc[i][2], ad, w2);
                fma2(acc[i][3], ad, w3);
            }
        }
        __syncthreads();
    }

#pragma unroll
    for (int i = 0; i < 8; i++) {
        int r = row0 + ty * 8 + i;
        if (r < M) {
            float v[8];
#pragma unroll
            for (int j = 0; j < 4; j++)
                unpack2(acc[i][j], v[2 * j], v[2 * j + 1]);
            uint4 o;
            o.x = f2bf(v[0], v[1]);
            o.y = f2bf(v[2], v[3]);
            o.z = f2bf(v[4], v[5]);
            o.w = f2bf(v[6], v[7]);
            ((uint4*)(g_p16 + (size_t)r * 128))[tx] = o;
        }
    }
}

// ------- agg1: g_h16 = bf16(relu(agg(g_p16) + b1)), one warp per node -----
// bf16 gather: one uint2 (4 bf16) per lane per row. MLP-16.
__global__ void k_agg(const float* __restrict__ bias, int n) {
    int gt = blockIdx.x * blockDim.x + threadIdx.x;
    int node = gt >> 5;
    if (node >= n) return;
    int lane = threadIdx.x & 31;
    const uint2* __restrict__ in = (const uint2*)g_p16;

    int e   = g_rowoff[node];
    int end = g_rowoff[node + 1];
    float4 acc = make_float4(0.f, 0.f, 0.f, 0.f);

    for (; e + 16 <= end; e += 16) {
        int si[16];
#pragma unroll
        for (int q = 0; q < 16; q++) si[q] = g_csrc[e + q];
        uint2 v[16];
#pragma unroll
        for (int q = 0; q < 16; q++)
            v[q] = __ldg(&in[(size_t)si[q] * 32 + lane]);
#pragma unroll
        for (int q = 0; q < 16; q++) {
            float2 lo = bf2f(v[q].x);
            float2 hi = bf2f(v[q].y);
            acc.x += lo.x; acc.y += lo.y; acc.z += hi.x; acc.w += hi.y;
        }
    }
    for (; e + 4 <= end; e += 4) {
        int s0 = g_csrc[e];
        int s1 = g_csrc[e + 1];
        int s2 = g_csrc[e + 2];
        int s3 = g_csrc[e + 3];
        uint2 v0 = __ldg(&in[(size_t)s0 * 32 + lane]);
        uint2 v1 = __ldg(&in[(size_t)s1 * 32 + lane]);
        uint2 v2 = __ldg(&in[(size_t)s2 * 32 + lane]);
        uint2 v3 = __ldg(&in[(size_t)s3 * 32 + lane]);
        float2 a0 = bf2f(v0.x), b0 = bf2f(v0.y);
        float2 a1 = bf2f(v1.x), b1_ = bf2f(v1.y);
        float2 a2 = bf2f(v2.x), b2_ = bf2f(v2.y);
        float2 a3 = bf2f(v3.x), b3 = bf2f(v3.y);
        acc.x += (a0.x + a1.x) + (a2.x + a3.x);
        acc.y += (a0.y + a1.y) + (a2.y + a3.y);
        acc.z += (b0.x + b1_.x) + (b2_.x + b3.x);
        acc.w += (b0.y + b1_.y) + (b2_.y + b3.y);
    }
    for (; e < end; e++) {
        int s0 = g_csrc[e];
        uint2 v0 = __ldg(&in[(size_t)s0 * 32 + lane]);
        float2 lo = bf2f(v0.x), hi = bf2f(v0.y);
        acc.x += lo.x; acc.y += lo.y; acc.z += hi.x; acc.w += hi.y;
    }
    float4 bb = __ldg(&((const float4*)bias)[lane]);
    acc.x = fmaxf(acc.x + bb.x, 0.f);
    acc.y = fmaxf(acc.y + bb.y, 0.f);
    acc.z = fmaxf(acc.z + bb.z, 0.f);
    acc.w = fmaxf(acc.w + bb.w, 0.f);
    uint2 o;
    o.x = f2bf(acc.x, acc.y);
    o.y = f2bf(acc.z, acc.w);
    ((uint2*)g_h16)[(size_t)node * 32 + lane] = o;
}

// ------- fused layer 2: g_bufA = relu(agg(g_h16) @ W2 + b2) ---------------
// R10 structure (128-node tile), bf16 gather in phase A.
#define FA_STRIDE 132
#define SM_FUSED  (128 * FA_STRIDE * 4 + 32 * 128 * 4)   // 83968 bytes
__global__ void __launch_bounds__(256) k_fused(const float* __restrict__ W,
                                               const float* __restrict__ bias, int N) {
    extern __shared__ float smem[];
    float* As = smem;                      // [128][FA_STRIDE]
    float* Ws = smem + 128 * FA_STRIDE;    // [32][128]

    int tid = threadIdx.x;
    int wid = tid >> 5;
    int lane = tid & 31;
    int row0 = blockIdx.x * 128;
    const uint2* __restrict__ in = (const uint2*)g_h16;
    float* __restrict__ out = g_bufA;

    // ---- Phase A: gather 16 nodes per warp into smem, bf16 rows, MLP-16 ----
    for (int j = 0; j < 16; j++) {
        int lr = wid * 16 + j;
        int node = row0 + lr;
        float4 acc = make_float4(0.f, 0.f, 0.f, 0.f);
        if (node < N) {
            int e   = g_rowoff[node];
            int end = g_rowoff[node + 1];
            for (; e + 16 <= end; e += 16) {
                int si[16];
#pragma unroll
                for (int q = 0; q < 16; q++) si[q] = g_csrc[e + q];
                uint2 v[16];
#pragma unroll
                for (int q = 0; q < 16; q++)
                    v[q] = __ldg(&in[(size_t)si[q] * 32 + lane]);
#pragma unroll
                for (int q = 0; q < 16; q++) {
                    float2 lo = bf2f(v[q].x);
                    float2 hi = bf2f(v[q].y);
                    acc.x += lo.x; acc.y += lo.y; acc.z += hi.x; acc.w += hi.y;
                }
            }
            for (; e + 4 <= end; e += 4) {
                int s0 = g_csrc[e];
                int s1 = g_csrc[e + 1];
                int s2 = g_csrc[e + 2];
                int s3 = g_csrc[e + 3];
                uint2 v0 = __ldg(&in[(size_t)s0 * 32 + lane]);
                uint2 v1 = __ldg(&in[(size_t)s1 * 32 + lane]);
                uint2 v2 = __ldg(&in[(size_t)s2 * 32 + lane]);
                uint2 v3 = __ldg(&in[(size_t)s3 * 32 + lane]);
                float2 a0 = bf2f(v0.x), b0 = bf2f(v0.y);
                float2 a1 = bf2f(v1.x), b1_ = bf2f(v1.y);
                float2 a2 = bf2f(v2.x), b2_ = bf2f(v2.y);
                float2 a3 = bf2f(v3.x), b3 = bf2f(v3.y);
                acc.x += (a0.x + a1.x) + (a2.x + a3.x);
                acc.y += (a0.y + a1.y) + (a2.y + a3.y);
                acc.z += (b0.x + b1_.x) + (b2_.x + b3.x);
                acc.w += (b0.y + b1_.y) + (b2_.y + b3.y);
            }
            for (; e < end; e++) {
                int s0 = g_csrc[e];
                uint2 v0 = __ldg(&in[(size_t)s0 * 32 + lane]);
                float2 lo = bf2f(v0.x), hi = bf2f(v0.y);
                acc.x += lo.x; acc.y += lo.y; acc.z += hi.x; acc.w += hi.y;
            }
        }
        *(float4*)&As[lr * FA_STRIDE + lane * 4] = acc;
    }
    __syncthreads();

    // ---- Phase B: GEMM from smem As, W tiles ----
    int tx = tid & 15;
    int ty = tid >> 4;

    uint64_t acc[8][4];
#pragma unroll
    for (int i = 0; i < 8; i++)
#pragma unroll
        for (int j = 0; j < 4; j++) acc[i][j] = 0ull;

    for (int kt = 0; kt < 4; kt++) {
        int k0 = kt * 32;
#pragma unroll
        for (int j = 0; j < 4; j++) {
            int lin = (j * 256 + tid) * 4;
            int r = lin >> 7;
            int c = lin & 127;
            *(float4*)&Ws[r * 128 + c] = *(const float4*)&W[(size_t)(k0 + r) * 128 + c];
        }
        __syncthreads();

#pragma unroll 8
        for (int kk = 0; kk < 32; kk++) {
            const uint64_t* wrow = (const uint64_t*)&Ws[kk * 128 + tx * 8];
            uint64_t w0 = wrow[0];
            uint64_t w1 = wrow[1];
            uint64_t w2 = wrow[2];
            uint64_t w3 = wrow[3];
#pragma unroll
            for (int i = 0; i < 8; i++) {
                float a = As[(ty * 8 + i) * FA_STRIDE + k0 + kk];
                uint64_t ad = pack2(a, a);
                fma2(acc[i][0], ad, w0);
                fma2(acc[i][1], ad, w1);
                fma2(acc[i][2], ad, w2);
                fma2(acc[i][3], ad, w3);
            }
        }
        __syncthreads();
    }

    float bb[8];
#pragma unroll
    for (int j = 0; j < 8; j++) bb[j] = __ldg(&bias[tx * 8 + j]);

#pragma unroll
    for (int i = 0; i < 8; i++) {
        int r = row0 + ty * 8 + i;
        if (r < N) {
            float v[8];
#pragma unroll
            for (int j = 0; j < 4; j++)
                unpack2(acc[i][j], v[2 * j], v[2 * j + 1]);
            float4 o0, o1;
            o0.x = fmaxf(v[0] + bb[0], 0.f);
            o0.y = fmaxf(v[1] + bb[1], 0.f);
            o0.z = fmaxf(v[2] + bb[2], 0.f);
            o0.w = fmaxf(v[3] + bb[3], 0.f);
            o1.x = fmaxf(v[4] + bb[4], 0.f);
            o1.y = fmaxf(v[5] + bb[5], 0.f);
            o1.z = fmaxf(v[6] + bb[6], 0.f);
            o1.w = fmaxf(v[7] + bb[7], 0.f);
            float4* orow = (float4*)&out[(size_t)r * 128 + tx * 8];
            orow[0] = o0;
            orow[1] = o1;
        }
    }
}

// ------- pooling: 8 CTAs per graph, atomic accumulate (reads h2 = g_bufA) -
__global__ void k_pool8(const int* __restrict__ gid, int n) {
    __shared__ int s_beg, s_end;
    int g = blockIdx.x >> 3;
    int slice = blockIdx.x & 7;
    if (threadIdx.x == 0) {
        int lo = 0, hi = n;
        while (lo < hi) { int mid = (lo + hi) >> 1; if (gid[mid] < g) lo = mid + 1; else hi = mid; }
        s_beg = lo;
        lo = 0; hi = n;
        while (lo < hi) { int mid = (lo + hi) >> 1; if (gid[mid] < g + 1) lo = mid + 1; else hi = mid; }
        s_end = lo;
    }
    __syncthreads();
    int beg = s_beg, end = s_end;
    int len = end - beg;
    int chunk = (len + 7) >> 3;
    int s = beg + slice * chunk;
    int e = s + chunk; if (e > end) e = end;
    if (s >= e) return;
    int f = threadIdx.x;
    const float* __restrict__ h = g_bufA;
    float acc = 0.f;
    int i = s;
    for (; i + 4 <= e; i += 4) {
        float a0 = h[(size_t)(i)     * 128 + f];
        float a1 = h[(size_t)(i + 1) * 128 + f];
        float a2 = h[(size_t)(i + 2) * 128 + f];
        float a3 = h[(size_t)(i + 3) * 128 + f];
        acc += (a0 + a1) + (a2 + a3);
    }
    for (; i < e; i++) acc += h[(size_t)i * 128 + f];
    atomicAdd(&g_gf[g * 128 + f], acc);
}

// ------- final projection ------------------
__global__ void k_final(const float* __restrict__ Wp, const float* __restrict__ bp,
                        float* __restrict__ out, const int* __restrict__ gid,
                        int n, int G, int C) {
    int tid = blockIdx.x * blockDim.x + threadIdx.x;
    if (tid >= G * C) return;
    int g = tid / C;
    int c = tid % C;
    int lo = 0, hi = n;
    while (lo < hi) { int mid = (lo + hi) >> 1; if (gid[mid] < g) lo = mid + 1; else hi = mid; }
    int beg = lo;
    lo = 0; hi = n;
    while (lo < hi) { int mid = (lo + hi) >> 1; if (gid[mid] < g + 1) lo = mid + 1; else hi = mid; }
    int cnt = lo - beg;
    float inv = 1.f / ((cnt > 0) ? (float)cnt : 1.f);
    float acc = 0.f;
#pragma unroll 8
    for (int k = 0; k < 128; k++)
        acc += (g_gf[g * 128 + k] * inv) * Wp[k * C + c];
    out[tid] = acc + bp[c];
}

// ---------------- launch --------------------------------------------------
extern "C" void kernel_launch(void* const* d_in, const int* in_sizes, int n_in,
                              void* d_out, int out_size) {
    const float* feat = (const float*)d_in[0];
    const float* W1   = (const float*)d_in[1];
    const float* b1   = (const float*)d_in[2];
    const float* W2   = (const float*)d_in[3];
    const float* b2   = (const float*)d_in[4];
    const float* Wp   = (const float*)d_in[5];
    const float* bp   = (const float*)d_in[6];
    const int*   src  = (const int*)d_in[7];
    const int*   dst  = (const int*)d_in[8];
    const int*   gid  = (const int*)d_in[9];

    int N = in_sizes[0] / HF;
    int E = in_sizes[7];
    int C = in_sizes[6];
    int G = out_size / C;

    static cudaStream_t s2 = nullptr;
    static cudaEvent_t evFork = nullptr, evCsr = nullptr;
    if (!s2) {
        cudaStreamCreateWithFlags(&s2, cudaStreamNonBlocking);
        cudaEventCreateWithFlags(&evFork, cudaEventDisableTiming);
        cudaEventCreateWithFlags(&evCsr, cudaEventDisableTiming);
        cudaFuncSetAttribute(k_fused, cudaFuncAttributeMaxDynamicSharedMemorySize, SM_FUSED);
    }

    int scanBlocks = (N + 255) / 256;

    // ---- fork: CSR build on s2, GEMM1 on main (single fork/join, proven) ----
    cudaEventRecord(evFork, 0);
    cudaStreamWaitEvent(s2, evFork, 0);

    k_zero   <<<(N + 255) / 256, 256, 0, s2>>>(N);
    k_hist4  <<<(E / 4 + 255) / 256, 256, 0, s2>>>(dst, E);
    k_scan1  <<<scanBlocks, 256, 0, s2>>>(N);
    k_scan2  <<<1, 512, 0, s2>>>(scanBlocks, N);
    k_scan3  <<<scanBlocks, 256, 0, s2>>>(N);
    k_bucket4<<<(E / 4 + 255) / 256, 256, 0, s2>>>(src, dst, E);
    cudaEventRecord(evCsr, s2);

    // GEMM1: P1 = bf16(feat @ W1) -> g_p16 (no CSR dependency)
    k_gemm<<<(N + 127) / 128, 256>>>(feat, W1, N);

    cudaStreamWaitEvent(0, evCsr, 0);

    // h1 = bf16(relu(agg(P1) + b1)): g_p16 -> g_h16
    k_agg<<<(N * 32 + 255) / 256, 256>>>(b1, N);

    // fused layer 2: h2 = relu(agg(h1) @ W2 + b2): g_h16 -> g_bufA
    k_fused<<<(N + 127) / 128, 256, SM_FUSED>>>(W2, b2, N);

    // readout (reads g_bufA = h2)
    k_pool8<<<G * 8, 128>>>(gid, N);
    k_final<<<(G * C + 255) / 256, 256>>>(Wp, bp, (float*)d_out, gid, N, G, C);
}

// round 14
// speedup vs baseline: 1.2013x; 1.0634x over previous
#include <cuda_runtime.h>
#include <cuda_bf16.h>
#include <cstdint>

// ---------------- problem-size constants ----------------
#define NMAX   100000
#define EMAX   1600000
#define HF     128
#define GMAX   64

// ---------------- static device scratch (ONLY touched inside kernels) -----
__device__ __nv_bfloat16 g_p16[(size_t)NMAX * HF];   // P1 in bf16
__device__ __nv_bfloat16 g_h16[(size_t)NMAX * HF];   // h1 in bf16
__device__ int   g_deg[NMAX];
__device__ int   g_rowoff[NMAX + 1];
__device__ int   g_cursor[NMAX];
__device__ int   g_csrc[EMAX];
__device__ int   g_part[512];
__device__ float g_gf[GMAX * HF];

// ---------------- packed helpers -----------------
static __device__ __forceinline__ uint64_t pack2(float x, float y) {
    uint64_t r;
    asm("mov.b64 %0, {%1, %2};" : "=l"(r) : "f"(x), "f"(y));
    return r;
}
static __device__ __forceinline__ void unpack2(uint64_t v, float& x, float& y) {
    asm("mov.b64 {%0, %1}, %2;" : "=f"(x), "=f"(y) : "l"(v));
}
static __device__ __forceinline__ void fma2(uint64_t& d, uint64_t a, uint64_t b) {
    asm("fma.rn.f32x2 %0, %1, %2, %0;" : "+l"(d) : "l"(a), "l"(b));
}
static __device__ __forceinline__ float2 bf2f(uint32_t u) {
    __nv_bfloat162 b = *reinterpret_cast<__nv_bfloat162*>(&u);
    return __bfloat1622float2(b);
}
static __device__ __forceinline__ uint32_t f2bf(float x, float y) {
    __nv_bfloat162 b = __float22bfloat162_rn(make_float2(x, y));
    return *reinterpret_cast<uint32_t*>(&b);
}

// ---------------- CSR build (stream 2) ----------------
__global__ void k_zero(int n) {
    int i = blockIdx.x * blockDim.x + threadIdx.x;
    if (i < n) g_deg[i] = 0;
    if (i < GMAX * HF) g_gf[i] = 0.f;
}

__global__ void k_hist4(const int* __restrict__ dst, int E) {
    int i4 = (blockIdx.x * blockDim.x + threadIdx.x) * 4;
    if (i4 + 4 <= E) {
        int4 d = *(const int4*)&dst[i4];
        atomicAdd(&g_deg[d.x], 1);
        atomicAdd(&g_deg[d.y], 1);
        atomicAdd(&g_deg[d.z], 1);
        atomicAdd(&g_deg[d.w], 1);
    } else {
        for (int i = i4; i < E; i++) atomicAdd(&g_deg[dst[i]], 1);
    }
}

__global__ void k_scan1(int n) {
    __shared__ int s[256];
    int i = blockIdx.x * 256 + threadIdx.x;
    s[threadIdx.x] = (i < n) ? g_deg[i] : 0;
    __syncthreads();
    for (int off = 128; off > 0; off >>= 1) {
        if (threadIdx.x < off) s[threadIdx.x] += s[threadIdx.x + off];
        __syncthreads();
    }
    if (threadIdx.x == 0) g_part[blockIdx.x] = s[0];
}
__global__ void k_scan2(int nb, int n) {
    __shared__ int s[512];
    int t = threadIdx.x;
    int v = (t < nb) ? g_part[t] : 0;
    s[t] = v;
    __syncthreads();
    for (int off = 1; off < 512; off <<= 1) {
        int x = s[t];
        int y = (t >= off) ? s[t - off] : 0;
        __syncthreads();
        s[t] = x + y;
        __syncthreads();
    }
    if (t < nb) g_part[t] = s[t] - v;
    if (t == 511) g_rowoff[n] = s[511];
}
__global__ void k_scan3(int n) {
    __shared__ int s[256];
    int t = threadIdx.x;
    int i = blockIdx.x * 256 + t;
    int v = (i < n) ? g_deg[i] : 0;
    s[t] = v;
    __syncthreads();
    for (int off = 1; off < 256; off <<= 1) {
        int x = s[t];
        int y = (t >= off) ? s[t - off] : 0;
        __syncthreads();
        s[t] = x + y;
        __syncthreads();
    }
    if (i < n) {
        int o = g_part[blockIdx.x] + s[t] - v;
        g_rowoff[i] = o;
        g_cursor[i] = o;
    }
}

__global__ void k_bucket4(const int* __restrict__ src, const int* __restrict__ dst, int E) {
    int i4 = (blockIdx.x * blockDim.x + threadIdx.x) * 4;
    if (i4 + 4 <= E) {
        int4 d = *(const int4*)&dst[i4];
        int4 sv = *(const int4*)&src[i4];
        int p0 = atomicAdd(&g_cursor[d.x], 1);
        int p1 = atomicAdd(&g_cursor[d.y], 1);
        int p2 = atomicAdd(&g_cursor[d.z], 1);
        int p3 = atomicAdd(&g_cursor[d.w], 1);
        g_csrc[p0] = sv.x;
        g_csrc[p1] = sv.y;
        g_csrc[p2] = sv.z;
        g_csrc[p3] = sv.w;
    } else {
        for (int i = i4; i < E; i++) {
            int p = atomicAdd(&g_cursor[dst[i]], 1);
            g_csrc[p] = src[i];
        }
    }
}

// ---------------- GEMM1: g_p16 = bf16(feat @ W1) --------------------------
#define AS_STRIDE 36
__global__ void __launch_bounds__(256) k_gemm(const float* __restrict__ A,
                                              const float* __restrict__ W, int M) {
    __shared__ float As[128 * AS_STRIDE];
    __shared__ float Ws[32 * 128];

    int tid = threadIdx.x;
    int tx = tid & 15;
    int ty = tid >> 4;
    int row0 = blockIdx.x * 128;

    uint64_t acc[8][4];
#pragma unroll
    for (int i = 0; i < 8; i++)
#pragma unroll
        for (int j = 0; j < 4; j++) acc[i][j] = 0ull;

    for (int kt = 0; kt < 4; kt++) {
        int k0 = kt * 32;
#pragma unroll
        for (int j = 0; j < 4; j++) {
            int lin = (j * 256 + tid) * 4;
            int r = lin >> 5;
            int c = lin & 31;
            float4 v = make_float4(0.f, 0.f, 0.f, 0.f);
            if (row0 + r < M)
                v = *(const float4*)&A[(size_t)(row0 + r) * 128 + k0 + c];
            *(float4*)&As[r * AS_STRIDE + c] = v;
        }
#pragma unroll
        for (int j = 0; j < 4; j++) {
            int lin = (j * 256 + tid) * 4;
            int r = lin >> 7;
            int c = lin & 127;
            *(float4*)&Ws[r * 128 + c] = *(const float4*)&W[(size_t)(k0 + r) * 128 + c];
        }
        __syncthreads();

#pragma unroll 8
        for (int kk = 0; kk < 32; kk++) {
            const uint64_t* wrow = (const uint64_t*)&Ws[kk * 128 + tx * 8];
            uint64_t w0 = wrow[0];
            uint64_t w1 = wrow[1];
            uint64_t w2 = wrow[2];
            uint64_t w3 = wrow[3];
#pragma unroll
            for (int i = 0; i < 8; i++) {
                float a = As[(ty * 8 + i) * AS_STRIDE + kk];
                uint64_t ad = pack2(a, a);
                fma2(acc[i][0], ad, w0);
                fma2(acc[i][1], ad, w1);
                fma2(acc[i][2], ad, w2);
                fma2(acc[i][3], ad, w3);
            }
        }
        __syncthreads();
    }

#pragma unroll
    for (int i = 0; i < 8; i++) {
        int r = row0 + ty * 8 + i;
        if (r < M) {
            float v[8];
#pragma unroll
            for (int j = 0; j < 4; j++)
                unpack2(acc[i][j], v[2 * j], v[2 * j + 1]);
            uint4 o;
            o.x = f2bf(v[0], v[1]);
            o.y = f2bf(v[2], v[3]);
            o.z = f2bf(v[4], v[5]);
            o.w = f2bf(v[6], v[7]);
            ((uint4*)(g_p16 + (size_t)r * 128))[tx] = o;
        }
    }
}

// ------- agg1: g_h16 = bf16(relu(agg(g_p16) + b1)), one warp per node -----
__global__ void k_agg(const float* __restrict__ bias, int n) {
    int gt = blockIdx.x * blockDim.x + threadIdx.x;
    int node = gt >> 5;
    if (node >= n) return;
    int lane = threadIdx.x & 31;
    const uint2* __restrict__ in = (const uint2*)g_p16;

    int e   = g_rowoff[node];
    int end = g_rowoff[node + 1];
    float4 acc = make_float4(0.f, 0.f, 0.f, 0.f);

    for (; e + 16 <= end; e += 16) {
        int si[16];
#pragma unroll
        for (int q = 0; q < 16; q++) si[q] = g_csrc[e + q];
        uint2 v[16];
#pragma unroll
        for (int q = 0; q < 16; q++)
            v[q] = __ldg(&in[(size_t)si[q] * 32 + lane]);
#pragma unroll
        for (int q = 0; q < 16; q++) {
            float2 lo = bf2f(v[q].x);
            float2 hi = bf2f(v[q].y);
            acc.x += lo.x; acc.y += lo.y; acc.z += hi.x; acc.w += hi.y;
        }
    }
    for (; e + 4 <= end; e += 4) {
        int s0 = g_csrc[e];
        int s1 = g_csrc[e + 1];
        int s2 = g_csrc[e + 2];
        int s3 = g_csrc[e + 3];
        uint2 v0 = __ldg(&in[(size_t)s0 * 32 + lane]);
        uint2 v1 = __ldg(&in[(size_t)s1 * 32 + lane]);
        uint2 v2 = __ldg(&in[(size_t)s2 * 32 + lane]);
        uint2 v3 = __ldg(&in[(size_t)s3 * 32 + lane]);
        float2 a0 = bf2f(v0.x), b0 = bf2f(v0.y);
        float2 a1 = bf2f(v1.x), b1_ = bf2f(v1.y);
        float2 a2 = bf2f(v2.x), b2_ = bf2f(v2.y);
        float2 a3 = bf2f(v3.x), b3 = bf2f(v3.y);
        acc.x += (a0.x + a1.x) + (a2.x + a3.x);
        acc.y += (a0.y + a1.y) + (a2.y + a3.y);
        acc.z += (b0.x + b1_.x) + (b2_.x + b3.x);
        acc.w += (b0.y + b1_.y) + (b2_.y + b3.y);
    }
    for (; e < end; e++) {
        int s0 = g_csrc[e];
        uint2 v0 = __ldg(&in[(size_t)s0 * 32 + lane]);
        float2 lo = bf2f(v0.x), hi = bf2f(v0.y);
        acc.x += lo.x; acc.y += lo.y; acc.z += hi.x; acc.w += hi.y;
    }
    float4 bb = __ldg(&((const float4*)bias)[lane]);
    acc.x = fmaxf(acc.x + bb.x, 0.f);
    acc.y = fmaxf(acc.y + bb.y, 0.f);
    acc.z = fmaxf(acc.z + bb.z, 0.f);
    acc.w = fmaxf(acc.w + bb.w, 0.f);
    uint2 o;
    o.x = f2bf(acc.x, acc.y);
    o.y = f2bf(acc.z, acc.w);
    ((uint2*)g_h16)[(size_t)node * 32 + lane] = o;
}

// ------- fused layer 2 + pooling: g_gf += colsums(relu(agg(g_h16)@W2+b2)) -
// Phase A: bf16 gather into smem. Phase B: f32x2 GEMM. Epilogue: h2 rows go
// to smem (As is dead), then per-feature serial reduction over the CTA's 128
// sorted-graph rows with ~1-2 atomicAdds per feature. h2 never hits global.
#define FA_STRIDE 132
#define SM_FUSED  (128 * FA_STRIDE * 4 + 32 * 128 * 4)   // 83968 bytes
__global__ void __launch_bounds__(256) k_fused(const float* __restrict__ W,
                                               const float* __restrict__ bias,
                                               const int* __restrict__ gid, int N) {
    extern __shared__ float smem[];
    float* As = smem;                      // [128][FA_STRIDE]
    float* Ws = smem + 128 * FA_STRIDE;    // [32][128]

    int tid = threadIdx.x;
    int wid = tid >> 5;
    int lane = tid & 31;
    int row0 = blockIdx.x * 128;
    const uint2* __restrict__ in = (const uint2*)g_h16;

    // ---- Phase A: gather 16 nodes per warp into smem, bf16 rows, MLP-16 ----
    for (int j = 0; j < 16; j++) {
        int lr = wid * 16 + j;
        int node = row0 + lr;
        float4 acc = make_float4(0.f, 0.f, 0.f, 0.f);
        if (node < N) {
            int e   = g_rowoff[node];
            int end = g_rowoff[node + 1];
            for (; e + 16 <= end; e += 16) {
                int si[16];
#pragma unroll
                for (int q = 0; q < 16; q++) si[q] = g_csrc[e + q];
                uint2 v[16];
#pragma unroll
                for (int q = 0; q < 16; q++)
                    v[q] = __ldg(&in[(size_t)si[q] * 32 + lane]);
#pragma unroll
                for (int q = 0; q < 16; q++) {
                    float2 lo = bf2f(v[q].x);
                    float2 hi = bf2f(v[q].y);
                    acc.x += lo.x; acc.y += lo.y; acc.z += hi.x; acc.w += hi.y;
                }
            }
            for (; e + 4 <= end; e += 4) {
                int s0 = g_csrc[e];
                int s1 = g_csrc[e + 1];
                int s2 = g_csrc[e + 2];
                int s3 = g_csrc[e + 3];
                uint2 v0 = __ldg(&in[(size_t)s0 * 32 + lane]);
                uint2 v1 = __ldg(&in[(size_t)s1 * 32 + lane]);
                uint2 v2 = __ldg(&in[(size_t)s2 * 32 + lane]);
                uint2 v3 = __ldg(&in[(size_t)s3 * 32 + lane]);
                float2 a0 = bf2f(v0.x), b0 = bf2f(v0.y);
                float2 a1 = bf2f(v1.x), b1_ = bf2f(v1.y);
                float2 a2 = bf2f(v2.x), b2_ = bf2f(v2.y);
                float2 a3 = bf2f(v3.x), b3 = bf2f(v3.y);
                acc.x += (a0.x + a1.x) + (a2.x + a3.x);
                acc.y += (a0.y + a1.y) + (a2.y + a3.y);
                acc.z += (b0.x + b1_.x) + (b2_.x + b3.x);
                acc.w += (b0.y + b1_.y) + (b2_.y + b3.y);
            }
            for (; e < end; e++) {
                int s0 = g_csrc[e];
                uint2 v0 = __ldg(&in[(size_t)s0 * 32 + lane]);
                float2 lo = bf2f(v0.x), hi = bf2f(v0.y);
                acc.x += lo.x; acc.y += lo.y; acc.z += hi.x; acc.w += hi.y;
            }
        }
        *(float4*)&As[lr * FA_STRIDE + lane * 4] = acc;
    }
    __syncthreads();

    // ---- Phase B: GEMM from smem As, W tiles ----
    int tx = tid & 15;
    int ty = tid >> 4;

    uint64_t acc[8][4];
#pragma unroll
    for (int i = 0; i < 8; i++)
#pragma unroll
        for (int j = 0; j < 4; j++) acc[i][j] = 0ull;

    for (int kt = 0; kt < 4; kt++) {
        int k0 = kt * 32;
#pragma unroll
        for (int j = 0; j < 4; j++) {
            int lin = (j * 256 + tid) * 4;
            int r = lin >> 7;
            int c = lin & 127;
            *(float4*)&Ws[r * 128 + c] = *(const float4*)&W[(size_t)(k0 + r) * 128 + c];
        }
        __syncthreads();

#pragma unroll 8
        for (int kk = 0; kk < 32; kk++) {
            const uint64_t* wrow = (const uint64_t*)&Ws[kk * 128 + tx * 8];
            uint64_t w0 = wrow[0];
            uint64_t w1 = wrow[1];
            uint64_t w2 = wrow[2];
            uint64_t w3 = wrow[3];
#pragma unroll
            for (int i = 0; i < 8; i++) {
                float a = As[(ty * 8 + i) * FA_STRIDE + k0 + kk];
                uint64_t ad = pack2(a, a);
                fma2(acc[i][0], ad, w0);
                fma2(acc[i][1], ad, w1);
                fma2(acc[i][2], ad, w2);
                fma2(acc[i][3], ad, w3);
            }
        }
        __syncthreads();
    }

    // ---- Epilogue: bias+ReLU into smem (As is dead) ----
    float bb[8];
#pragma unroll
    for (int j = 0; j < 8; j++) bb[j] = __ldg(&bias[tx * 8 + j]);

#pragma unroll
    for (int i = 0; i < 8; i++) {
        int lr = ty * 8 + i;
        float v[8];
#pragma unroll
        for (int j = 0; j < 4; j++)
            unpack2(acc[i][j], v[2 * j], v[2 * j + 1]);
        float4 o0, o1;
        o0.x = fmaxf(v[0] + bb[0], 0.f);
        o0.y = fmaxf(v[1] + bb[1], 0.f);
        o0.z = fmaxf(v[2] + bb[2], 0.f);
        o0.w = fmaxf(v[3] + bb[3], 0.f);
        o1.x = fmaxf(v[4] + bb[4], 0.f);
        o1.y = fmaxf(v[5] + bb[5], 0.f);
        o1.z = fmaxf(v[6] + bb[6], 0.f);
        o1.w = fmaxf(v[7] + bb[7], 0.f);
        *(float4*)&As[lr * FA_STRIDE + tx * 8]     = o0;
        *(float4*)&As[lr * FA_STRIDE + tx * 8 + 4] = o1;
    }

    // gid window into smem (reuse Ws)
    int* gids = (int*)Ws;
    if (tid < 128) {
        int node = row0 + tid;
        gids[tid] = (node < N) ? __ldg(&gid[node]) : -1;
    }
    __syncthreads();

    // ---- Pool: one feature per thread, serial over sorted rows ----
    if (tid < 128) {
        int f = tid;
        float run = 0.f;
        int curg = gids[0];
        for (int r = 0; r < 128; r++) {
            int gg = gids[r];
            if (gg < 0) break;
            if (gg != curg) {
                atomicAdd(&g_gf[curg * 128 + f], run);
                run = 0.f;
                curg = gg;
            }
            run += As[r * FA_STRIDE + f];
        }
        if (curg >= 0) atomicAdd(&g_gf[curg * 128 + f], run);
    }
}

// ------- final projection ------------------
__global__ void k_final(const float* __restrict__ Wp, const float* __restrict__ bp,
                        float* __restrict__ out, const int* __restrict__ gid,
                        int n, int G, int C) {
    int tid = blockIdx.x * blockDim.x + threadIdx.x;
    if (tid >= G * C) return;
    int g = tid / C;
    int c = tid % C;
    int lo = 0, hi = n;
    while (lo < hi) { int mid = (lo + hi) >> 1; if (gid[mid] < g) lo = mid + 1; else hi = mid; }
    int beg = lo;
    lo = 0; hi = n;
    while (lo < hi) { int mid = (lo + hi) >> 1; if (gid[mid] < g + 1) lo = mid + 1; else hi = mid; }
    int cnt = lo - beg;
    float inv = 1.f / ((cnt > 0) ? (float)cnt : 1.f);
    float acc = 0.f;
#pragma unroll 8
    for (int k = 0; k < 128; k++)
        acc += (g_gf[g * 128 + k] * inv) * Wp[k * C + c];
    out[tid] = acc + bp[c];
}

// ---------------- launch --------------------------------------------------
extern "C" void kernel_launch(void* const* d_in, const int* in_sizes, int n_in,
                              void* d_out, int out_size) {
    const float* feat = (const float*)d_in[0];
    const float* W1   = (const float*)d_in[1];
    const float* b1   = (const float*)d_in[2];
    const float* W2   = (const float*)d_in[3];
    const float* b2   = (const float*)d_in[4];
    const float* Wp   = (const float*)d_in[5];
    const float* bp   = (const float*)d_in[6];
    const int*   src  = (const int*)d_in[7];
    const int*   dst  = (const int*)d_in[8];
    const int*   gid  = (const int*)d_in[9];

    int N = in_sizes[0] / HF;
    int E = in_sizes[7];
    int C = in_sizes[6];
    int G = out_size / C;

    static cudaStream_t s2 = nullptr;
    static cudaEvent_t evFork = nullptr, evCsr = nullptr;
    if (!s2) {
        cudaStreamCreateWithFlags(&s2, cudaStreamNonBlocking);
        cudaEventCreateWithFlags(&evFork, cudaEventDisableTiming);
        cudaEventCreateWithFlags(&evCsr, cudaEventDisableTiming);
        cudaFuncSetAttribute(k_fused, cudaFuncAttributeMaxDynamicSharedMemorySize, SM_FUSED);
    }

    int scanBlocks = (N + 255) / 256;

    // ---- fork: CSR build on s2, GEMM1 on main (single fork/join, proven) ----
    cudaEventRecord(evFork, 0);
    cudaStreamWaitEvent(s2, evFork, 0);

    k_zero   <<<(N + 255) / 256, 256, 0, s2>>>(N);
    k_hist4  <<<(E / 4 + 255) / 256, 256, 0, s2>>>(dst, E);
    k_scan1  <<<scanBlocks, 256, 0, s2>>>(N);
    k_scan2  <<<1, 512, 0, s2>>>(scanBlocks, N);
    k_scan3  <<<scanBlocks, 256, 0, s2>>>(N);
    k_bucket4<<<(E / 4 + 255) / 256, 256, 0, s2>>>(src, dst, E);
    cudaEventRecord(evCsr, s2);

    // GEMM1: P1 = bf16(feat @ W1) -> g_p16 (no CSR dependency)
    k_gemm<<<(N + 127) / 128, 256>>>(feat, W1, N);

    cudaStreamWaitEvent(0, evCsr, 0);

    // h1 = bf16(relu(agg(P1) + b1)): g_p16 -> g_h16
    k_agg<<<(N * 32 + 255) / 256, 256>>>(b1, N);

    // fused layer 2 + pooling: g_h16 -> g_gf (h2 never leaves smem)
    k_fused<<<(N + 127) / 128, 256, SM_FUSED>>>(W2, b2, gid, N);

    // final projection
    k_final<<<(G * C + 255) / 256, 256>>>(Wp, bp, (float*)d_out, gid, N, G, C);
}